// round 12
// baseline (speedup 1.0000x reference)
#include <cuda_runtime.h>
#include <cuda_bf16.h>
#include <cstdint>

#define NN 50000
#define EE 800000

__device__ float g_buf0[NN * 96];
__device__ float g_buf1[NN * 96];
__device__ int   g_deg[NN];       // zero-init at load; re-zeroed by k_scan1 each run
__device__ float g_dinv[NN];
__device__ int   g_off[NN + 1];
__device__ int   g_cur[NN];
__device__ int   g_esrc[EE];
__device__ int   g_bsum[64];

__global__ void k_count(const int* __restrict__ dst) {
    int e = blockIdx.x * blockDim.x + threadIdx.x;
    if (e < EE) atomicAdd(&g_deg[dst[e]], 1);
}

// block-level exclusive scan of degrees; also computes dinv and RE-ZEROES g_deg
// so the next graph replay starts from a clean histogram.
__global__ void k_scan1() {
    __shared__ int sh[1024];
    int t = threadIdx.x;
    int i = blockIdx.x * 1024 + t;
    int dg = (i < NN) ? g_deg[i] : 0;
    sh[t] = dg;
    for (int o = 1; o < 1024; o <<= 1) {
        __syncthreads();
        int tmp = (t >= o) ? sh[t - o] : 0;
        __syncthreads();
        sh[t] += tmp;
    }
    __syncthreads();
    if (i < NN) {
        g_off[i] = sh[t] - dg;
        g_dinv[i] = rsqrtf((float)(dg + 1));   // +1 self-loop
        g_deg[i] = 0;                          // reset for next replay
    }
    if (t == 1023) g_bsum[blockIdx.x] = sh[1023];
}

// finalize offsets: warp-parallel exclusive prefix of <=64 block sums
__global__ void k_scan3(int nb) {
    __shared__ int sb[65];
    int t = threadIdx.x;
    if (t < 64) {
        int v = (t < nb) ? g_bsum[t] : 0;
        int lane = t & 31;
#pragma unroll
        for (int o = 1; o < 32; o <<= 1) {
            int u = __shfl_up_sync(0xFFFFFFFF, v, o);
            if (lane >= o) v += u;
        }
        sb[t + 1] = v;
    }
    __syncthreads();
    if (t == 0) sb[0] = 0;
    if (t >= 32 && t < 64) sb[t + 1] += sb[32];
    __syncthreads();
    int i = blockIdx.x * blockDim.x + threadIdx.x;
    if (i < NN) {
        int o = g_off[i] + sb[i >> 10];
        g_off[i] = o;
        g_cur[i] = o;
    }
    if (i == 0) g_off[NN] = EE;
}

__global__ void k_fill(const int* __restrict__ src, const int* __restrict__ dst) {
    int e = blockIdx.x * blockDim.x + threadIdx.x;
    if (e < EE) {
        int d = dst[e];
        int p = atomicAdd(&g_cur[d], 1);
        g_esrc[p] = src[e];
    }
}

#define MMA_BF16(C, A, B)                                                        \
    asm volatile(                                                                \
        "mma.sync.aligned.m16n8k16.row.col.f32.bf16.bf16.f32 "                   \
        "{%0,%1,%2,%3}, {%4,%5,%6,%7}, {%8,%9}, {%0,%1,%2,%3};"                  \
        : "+f"(C[0]), "+f"(C[1]), "+f"(C[2]), "+f"(C[3])                         \
        : "r"(A[0]), "r"(A[1]), "r"(A[2]), "r"(A[3]), "r"(B[0]), "r"(B[1]))

template <int FOUT>
__global__ __launch_bounds__(256) void k_gemm_mma(const float* __restrict__ Xext,
                                                  const float* __restrict__ W,
                                                  int in_sel, int K, int relu_in) {
    const float* X = (in_sel == 0) ? Xext : (const float*)g_buf1;
    constexpr int PAD = 40;
    __shared__ __align__(16) __nv_bfloat16 sAh[128 * PAD];
    __shared__ __align__(16) __nv_bfloat16 sAl[128 * PAD];
    __shared__ __align__(16) __nv_bfloat16 sBh[FOUT * PAD];
    __shared__ __align__(16) __nv_bfloat16 sBl[FOUT * PAD];
    const int t = threadIdx.x, lane = t & 31, warp = t >> 5;
    const int gid = lane >> 2, tig = lane & 3;
    const int row0 = blockIdx.x * 128;
    constexpr int NT = FOUT / 8;
    float acc[NT][4];
#pragma unroll
    for (int n = 0; n < NT; n++)
#pragma unroll
        for (int c = 0; c < 4; c++) acc[n][c] = 0.f;

    for (int k0 = 0; k0 < K; k0 += 32) {
        __syncthreads();
        for (int i = t; i < 128 * 16; i += 256) {
            int r = i >> 4, kp = (i & 15) << 1;
            float2 v = make_float2(0.f, 0.f);
            int row = row0 + r;
            if (row < NN) v = *(const float2*)&X[row * K + k0 + kp];
            if (relu_in) { v.x = fmaxf(v.x, 0.f); v.y = fmaxf(v.y, 0.f); }
            __nv_bfloat16 h0 = __float2bfloat16(v.x), h1 = __float2bfloat16(v.y);
            __nv_bfloat16 l0 = __float2bfloat16(v.x - __bfloat162float(h0));
            __nv_bfloat16 l1 = __float2bfloat16(v.y - __bfloat162float(h1));
            *(__nv_bfloat162*)&sAh[r * PAD + kp] = __halves2bfloat162(h0, h1);
            *(__nv_bfloat162*)&sAl[r * PAD + kp] = __halves2bfloat162(l0, l1);
        }
        for (int i = t; i < 32 * FOUT; i += 256) {
            int kk = i / FOUT, n = i - kk * FOUT;
            float w = W[(k0 + kk) * FOUT + n];
            __nv_bfloat16 h = __float2bfloat16(w);
            sBh[n * PAD + kk] = h;
            sBl[n * PAD + kk] = __float2bfloat16(w - __bfloat162float(h));
        }
        __syncthreads();
#pragma unroll
        for (int ks = 0; ks < 32; ks += 16) {
            const __nv_bfloat16* pa = &sAh[(warp * 16 + gid) * PAD + ks + tig * 2];
            const __nv_bfloat16* pl = &sAl[(warp * 16 + gid) * PAD + ks + tig * 2];
            uint32_t ah[4], al[4];
            ah[0] = *(const uint32_t*)pa;
            ah[1] = *(const uint32_t*)(pa + 8 * PAD);
            ah[2] = *(const uint32_t*)(pa + 8);
            ah[3] = *(const uint32_t*)(pa + 8 * PAD + 8);
            al[0] = *(const uint32_t*)pl;
            al[1] = *(const uint32_t*)(pl + 8 * PAD);
            al[2] = *(const uint32_t*)(pl + 8);
            al[3] = *(const uint32_t*)(pl + 8 * PAD + 8);
#pragma unroll
            for (int nt = 0; nt < NT; nt++) {
                const __nv_bfloat16* pb = &sBh[(nt * 8 + gid) * PAD + ks + tig * 2];
                const __nv_bfloat16* pq = &sBl[(nt * 8 + gid) * PAD + ks + tig * 2];
                uint32_t bh[2], bl[2];
                bh[0] = *(const uint32_t*)pb;
                bh[1] = *(const uint32_t*)(pb + 8);
                bl[0] = *(const uint32_t*)pq;
                bl[1] = *(const uint32_t*)(pq + 8);
                MMA_BF16(acc[nt], ah, bh);
                MMA_BF16(acc[nt], al, bh);
                MMA_BF16(acc[nt], ah, bl);
            }
        }
    }
    int rA = row0 + warp * 16 + gid;
    int rB = rA + 8;
    float dA = (rA < NN) ? g_dinv[rA] : 0.f;
    float dB = (rB < NN) ? g_dinv[rB] : 0.f;
#pragma unroll
    for (int nt = 0; nt < NT; nt++) {
        int col = nt * 8 + tig * 2;
        if (rA < NN)
            *(float2*)&g_buf0[rA * FOUT + col] =
                make_float2(dA * acc[nt][0], dA * acc[nt][1]);
        if (rB < NN)
            *(float2*)&g_buf0[rB * FOUT + col] =
                make_float2(dB * acc[nt][2], dB * acc[nt][3]);
    }
}

// ---------------- aggregation (R8 forms — LTS-bandwidth-bound) ----------------
__global__ void k_agg96(const float* __restrict__ bias) {
    int wid = (blockIdx.x * blockDim.x + threadIdx.x) >> 5;
    int lane = threadIdx.x & 31;
    if (wid >= NN) return;
    int d = wid;
    int beg = g_off[d], end = g_off[d + 1];
    const float4* x4 = (const float4*)g_buf0;
    float4 acc = make_float4(0.f, 0.f, 0.f, 0.f);
    if (lane < 24) acc = x4[d * 24 + lane];
    for (int e = beg; e < end; e++) {
        int s = g_esrc[e];
        if (lane < 24) {
            float4 v = __ldg(&x4[s * 24 + lane]);
            acc.x += v.x; acc.y += v.y; acc.z += v.z; acc.w += v.w;
        }
    }
    if (lane < 24) {
        float sc = g_dinv[d];
        float4 b = ((const float4*)bias)[lane];
        float4 o;
        o.x = sc * acc.x + b.x; o.y = sc * acc.y + b.y;
        o.z = sc * acc.z + b.z; o.w = sc * acc.w + b.w;
        ((float4*)g_buf1)[d * 24 + lane] = o;
    }
}

__global__ void k_agg32lsm(const float* __restrict__ bias, float* __restrict__ out) {
    int wid = (blockIdx.x * blockDim.x + threadIdx.x) >> 5;
    int lane = threadIdx.x & 31;
    if (wid >= NN) return;
    int d = wid;
    int grp = lane >> 3, fl = lane & 7;
    const float4* x4 = (const float4*)g_buf0;
    float4 acc = make_float4(0.f, 0.f, 0.f, 0.f);
    if (grp == 0) acc = x4[d * 8 + fl];
    int beg = g_off[d], end = g_off[d + 1];
    for (int e = beg + grp; e < end; e += 4) {
        int s = g_esrc[e];
        float4 v = __ldg(&x4[s * 8 + fl]);
        acc.x += v.x; acc.y += v.y; acc.z += v.z; acc.w += v.w;
    }
#pragma unroll
    for (int o = 8; o <= 16; o <<= 1) {
        acc.x += __shfl_xor_sync(0xFFFFFFFF, acc.x, o);
        acc.y += __shfl_xor_sync(0xFFFFFFFF, acc.y, o);
        acc.z += __shfl_xor_sync(0xFFFFFFFF, acc.z, o);
        acc.w += __shfl_xor_sync(0xFFFFFFFF, acc.w, o);
    }
    float sc = g_dinv[d];
    float4 b = ((const float4*)bias)[fl];
    float4 v;
    v.x = sc * acc.x + b.x; v.y = sc * acc.y + b.y;
    v.z = sc * acc.z + b.z; v.w = sc * acc.w + b.w;
    float m = fmaxf(fmaxf(v.x, v.y), fmaxf(v.z, v.w));
#pragma unroll
    for (int o = 1; o <= 4; o <<= 1) m = fmaxf(m, __shfl_xor_sync(0xFFFFFFFF, m, o));
    float s = expf(v.x - m) + expf(v.y - m) + expf(v.z - m) + expf(v.w - m);
#pragma unroll
    for (int o = 1; o <= 4; o <<= 1) s += __shfl_xor_sync(0xFFFFFFFF, s, o);
    float ls = m + logf(s);
    if (grp == 0) {
        float4 o4 = make_float4(v.x - ls, v.y - ls, v.z - ls, v.w - ls);
        ((float4*)out)[d * 8 + fl] = o4;
    }
}

extern "C" void kernel_launch(void* const* d_in, const int* in_sizes, int n_in,
                              void* d_out, int out_size) {
    const float* x  = (const float*)d_in[0];
    const int*   ei = (const int*)d_in[1];
    const float* W1 = (const float*)d_in[2];
    const float* b1 = (const float*)d_in[3];
    const float* W2 = (const float*)d_in[4];
    const float* b2 = (const float*)d_in[5];
    const float* W3 = (const float*)d_in[6];
    const float* b3 = (const float*)d_in[7];
    float* out = (float*)d_out;

    const int* src = ei;
    const int* dst = ei + EE;

    const int NB_SCAN = (NN + 1023) / 1024;
    const int GT = (NN + 127) / 128;
    const int AB = (NN * 32 + 255) / 256;

    // CSR build (g_deg is zeroed: zero-init at load, re-zeroed by k_scan1 each run)
    k_count<<<(EE + 511) / 512, 512>>>(dst);
    k_scan1<<<NB_SCAN, 1024>>>();
    k_scan3<<<(NN + 255) / 256, 256>>>(NB_SCAN);
    k_fill<<<(EE + 511) / 512, 512>>>(src, dst);

    // layers
    k_gemm_mma<96><<<GT, 256>>>(x, W1, 0, 128, 0);
    k_agg96<<<AB, 256>>>(b1);
    k_gemm_mma<96><<<GT, 256>>>(x, W2, 1, 96, 1);
    k_agg96<<<AB, 256>>>(b2);
    k_gemm_mma<32><<<GT, 256>>>(x, W3, 1, 96, 1);
    k_agg32lsm<<<AB, 256>>>(b3, out);
}

// round 15
// speedup vs baseline: 1.3702x; 1.3702x over previous
#include <cuda_runtime.h>
#include <cuda_bf16.h>
#include <cstdint>

#define NN 50000
#define EE 800000

__device__ float g_buf0[NN * 96];
__device__ float g_buf1[NN * 96];
__device__ int   g_deg[NN];       // zero-init at load; re-zeroed by k_scan3 each run
__device__ float g_dinv[NN];
__device__ int   g_off[NN + 1];
__device__ int   g_cur[NN];
__device__ int   g_esrc[EE];
__device__ int   g_bsum[64];

__global__ void k_count(const int* __restrict__ dst) {
    int e = blockIdx.x * blockDim.x + threadIdx.x;
    if (e < EE) atomicAdd(&g_deg[dst[e]], 1);
}

// block-level exclusive scan of degrees (1024-thread blocks -> 49 block sums)
__global__ void k_scan1() {
    __shared__ int sh[1024];
    int t = threadIdx.x;
    int i = blockIdx.x * 1024 + t;
    int dg = (i < NN) ? g_deg[i] : 0;
    sh[t] = dg;
    for (int o = 1; o < 1024; o <<= 1) {
        __syncthreads();
        int tmp = (t >= o) ? sh[t - o] : 0;
        __syncthreads();
        sh[t] += tmp;
    }
    __syncthreads();
    if (i < NN) g_off[i] = sh[t] - dg;
    if (t == 1023) g_bsum[blockIdx.x] = sh[1023];
}

// finalize: warp-parallel exclusive prefix of <=64 block sums, then offsets,
// dinv, and g_deg reset (so the next graph replay starts clean).
__global__ void k_scan3(int nb) {
    __shared__ int sb[65];
    int t = threadIdx.x;
    if (t < 64) {
        int v = (t < nb) ? g_bsum[t] : 0;
        int lane = t & 31;
#pragma unroll
        for (int o = 1; o < 32; o <<= 1) {
            int u = __shfl_up_sync(0xFFFFFFFF, v, o);
            if (lane >= o) v += u;
        }
        sb[t + 1] = v;
    }
    __syncthreads();
    if (t == 0) sb[0] = 0;
    if (t >= 32 && t < 64) sb[t + 1] += sb[32];
    __syncthreads();
    int i = blockIdx.x * blockDim.x + threadIdx.x;
    if (i < NN) {
        int o = g_off[i] + sb[i >> 10];
        g_off[i] = o;
        g_cur[i] = o;
        g_dinv[i] = rsqrtf((float)(g_deg[i] + 1));   // +1 self-loop
        g_deg[i] = 0;                                // reset for next replay
    }
    if (i == 0) g_off[NN] = EE;
}

__global__ void k_fill(const int* __restrict__ src, const int* __restrict__ dst) {
    int e = blockIdx.x * blockDim.x + threadIdx.x;
    if (e < EE) {
        int d = dst[e];
        int p = atomicAdd(&g_cur[d], 1);
        g_esrc[p] = src[e];
    }
}

#define MMA_BF16(C, A, B)                                                        \
    asm volatile(                                                                \
        "mma.sync.aligned.m16n8k16.row.col.f32.bf16.bf16.f32 "                   \
        "{%0,%1,%2,%3}, {%4,%5,%6,%7}, {%8,%9}, {%0,%1,%2,%3};"                  \
        : "+f"(C[0]), "+f"(C[1]), "+f"(C[2]), "+f"(C[3])                         \
        : "r"(A[0]), "r"(A[1]), "r"(A[2]), "r"(A[3]), "r"(B[0]), "r"(B[1]))

template <int FOUT>
__global__ __launch_bounds__(256) void k_gemm_mma(const float* __restrict__ Xext,
                                                  const float* __restrict__ W,
                                                  int in_sel, int K, int relu_in) {
    const float* X = (in_sel == 0) ? Xext : (const float*)g_buf1;
    constexpr int PAD = 40;
    __shared__ __align__(16) __nv_bfloat16 sAh[128 * PAD];
    __shared__ __align__(16) __nv_bfloat16 sAl[128 * PAD];
    __shared__ __align__(16) __nv_bfloat16 sBh[FOUT * PAD];
    __shared__ __align__(16) __nv_bfloat16 sBl[FOUT * PAD];
    const int t = threadIdx.x, lane = t & 31, warp = t >> 5;
    const int gid = lane >> 2, tig = lane & 3;
    const int row0 = blockIdx.x * 128;
    constexpr int NT = FOUT / 8;
    float acc[NT][4];
#pragma unroll
    for (int n = 0; n < NT; n++)
#pragma unroll
        for (int c = 0; c < 4; c++) acc[n][c] = 0.f;

    for (int k0 = 0; k0 < K; k0 += 32) {
        __syncthreads();
        for (int i = t; i < 128 * 16; i += 256) {
            int r = i >> 4, kp = (i & 15) << 1;
            float2 v = make_float2(0.f, 0.f);
            int row = row0 + r;
            if (row < NN) v = *(const float2*)&X[row * K + k0 + kp];
            if (relu_in) { v.x = fmaxf(v.x, 0.f); v.y = fmaxf(v.y, 0.f); }
            __nv_bfloat16 h0 = __float2bfloat16(v.x), h1 = __float2bfloat16(v.y);
            __nv_bfloat16 l0 = __float2bfloat16(v.x - __bfloat162float(h0));
            __nv_bfloat16 l1 = __float2bfloat16(v.y - __bfloat162float(h1));
            *(__nv_bfloat162*)&sAh[r * PAD + kp] = __halves2bfloat162(h0, h1);
            *(__nv_bfloat162*)&sAl[r * PAD + kp] = __halves2bfloat162(l0, l1);
        }
        for (int i = t; i < 32 * FOUT; i += 256) {
            int kk = i / FOUT, n = i - kk * FOUT;
            float w = W[(k0 + kk) * FOUT + n];
            __nv_bfloat16 h = __float2bfloat16(w);
            sBh[n * PAD + kk] = h;
            sBl[n * PAD + kk] = __float2bfloat16(w - __bfloat162float(h));
        }
        __syncthreads();
#pragma unroll
        for (int ks = 0; ks < 32; ks += 16) {
            const __nv_bfloat16* pa = &sAh[(warp * 16 + gid) * PAD + ks + tig * 2];
            const __nv_bfloat16* pl = &sAl[(warp * 16 + gid) * PAD + ks + tig * 2];
            uint32_t ah[4], al[4];
            ah[0] = *(const uint32_t*)pa;
            ah[1] = *(const uint32_t*)(pa + 8 * PAD);
            ah[2] = *(const uint32_t*)(pa + 8);
            ah[3] = *(const uint32_t*)(pa + 8 * PAD + 8);
            al[0] = *(const uint32_t*)pl;
            al[1] = *(const uint32_t*)(pl + 8 * PAD);
            al[2] = *(const uint32_t*)(pl + 8);
            al[3] = *(const uint32_t*)(pl + 8 * PAD + 8);
#pragma unroll
            for (int nt = 0; nt < NT; nt++) {
                const __nv_bfloat16* pb = &sBh[(nt * 8 + gid) * PAD + ks + tig * 2];
                const __nv_bfloat16* pq = &sBl[(nt * 8 + gid) * PAD + ks + tig * 2];
                uint32_t bh[2], bl[2];
                bh[0] = *(const uint32_t*)pb;
                bh[1] = *(const uint32_t*)(pb + 8);
                bl[0] = *(const uint32_t*)pq;
                bl[1] = *(const uint32_t*)(pq + 8);
                MMA_BF16(acc[nt], ah, bh);
                MMA_BF16(acc[nt], al, bh);
                MMA_BF16(acc[nt], ah, bl);
            }
        }
    }
    int rA = row0 + warp * 16 + gid;
    int rB = rA + 8;
    float dA = (rA < NN) ? g_dinv[rA] : 0.f;
    float dB = (rB < NN) ? g_dinv[rB] : 0.f;
#pragma unroll
    for (int nt = 0; nt < NT; nt++) {
        int col = nt * 8 + tig * 2;
        if (rA < NN)
            *(float2*)&g_buf0[rA * FOUT + col] =
                make_float2(dA * acc[nt][0], dA * acc[nt][1]);
        if (rB < NN)
            *(float2*)&g_buf0[rB * FOUT + col] =
                make_float2(dB * acc[nt][2], dB * acc[nt][3]);
    }
}

// ---------------- aggregation (R8 forms — LTS-bandwidth-bound) ----------------
__global__ void k_agg96(const float* __restrict__ bias) {
    int wid = (blockIdx.x * blockDim.x + threadIdx.x) >> 5;
    int lane = threadIdx.x & 31;
    if (wid >= NN) return;
    int d = wid;
    int beg = g_off[d], end = g_off[d + 1];
    const float4* x4 = (const float4*)g_buf0;
    float4 acc = make_float4(0.f, 0.f, 0.f, 0.f);
    if (lane < 24) acc = x4[d * 24 + lane];
    for (int e = beg; e < end; e++) {
        int s = g_esrc[e];
        if (lane < 24) {
            float4 v = __ldg(&x4[s * 24 + lane]);
            acc.x += v.x; acc.y += v.y; acc.z += v.z; acc.w += v.w;
        }
    }
    if (lane < 24) {
        float sc = g_dinv[d];
        float4 b = ((const float4*)bias)[lane];
        float4 o;
        o.x = sc * acc.x + b.x; o.y = sc * acc.y + b.y;
        o.z = sc * acc.z + b.z; o.w = sc * acc.w + b.w;
        ((float4*)g_buf1)[d * 24 + lane] = o;
    }
}

__global__ void k_agg32lsm(const float* __restrict__ bias, float* __restrict__ out) {
    int wid = (blockIdx.x * blockDim.x + threadIdx.x) >> 5;
    int lane = threadIdx.x & 31;
    if (wid >= NN) return;
    int d = wid;
    int grp = lane >> 3, fl = lane & 7;
    const float4* x4 = (const float4*)g_buf0;
    float4 acc = make_float4(0.f, 0.f, 0.f, 0.f);
    if (grp == 0) acc = x4[d * 8 + fl];
    int beg = g_off[d], end = g_off[d + 1];
    for (int e = beg + grp; e < end; e += 4) {
        int s = g_esrc[e];
        float4 v = __ldg(&x4[s * 8 + fl]);
        acc.x += v.x; acc.y += v.y; acc.z += v.z; acc.w += v.w;
    }
#pragma unroll
    for (int o = 8; o <= 16; o <<= 1) {
        acc.x += __shfl_xor_sync(0xFFFFFFFF, acc.x, o);
        acc.y += __shfl_xor_sync(0xFFFFFFFF, acc.y, o);
        acc.z += __shfl_xor_sync(0xFFFFFFFF, acc.z, o);
        acc.w += __shfl_xor_sync(0xFFFFFFFF, acc.w, o);
    }
    float sc = g_dinv[d];
    float4 b = ((const float4*)bias)[fl];
    float4 v;
    v.x = sc * acc.x + b.x; v.y = sc * acc.y + b.y;
    v.z = sc * acc.z + b.z; v.w = sc * acc.w + b.w;
    float m = fmaxf(fmaxf(v.x, v.y), fmaxf(v.z, v.w));
#pragma unroll
    for (int o = 1; o <= 4; o <<= 1) m = fmaxf(m, __shfl_xor_sync(0xFFFFFFFF, m, o));
    float s = expf(v.x - m) + expf(v.y - m) + expf(v.z - m) + expf(v.w - m);
#pragma unroll
    for (int o = 1; o <= 4; o <<= 1) s += __shfl_xor_sync(0xFFFFFFFF, s, o);
    float ls = m + logf(s);
    if (grp == 0) {
        float4 o4 = make_float4(v.x - ls, v.y - ls, v.z - ls, v.w - ls);
        ((float4*)out)[d * 8 + fl] = o4;
    }
}

extern "C" void kernel_launch(void* const* d_in, const int* in_sizes, int n_in,
                              void* d_out, int out_size) {
    const float* x  = (const float*)d_in[0];
    const int*   ei = (const int*)d_in[1];
    const float* W1 = (const float*)d_in[2];
    const float* b1 = (const float*)d_in[3];
    const float* W2 = (const float*)d_in[4];
    const float* b2 = (const float*)d_in[5];
    const float* W3 = (const float*)d_in[6];
    const float* b3 = (const float*)d_in[7];
    float* out = (float*)d_out;

    const int* src = ei;
    const int* dst = ei + EE;

    const int NB_SCAN = (NN + 1023) / 1024;
    const int GT = (NN + 127) / 128;
    const int AB = (NN * 32 + 255) / 256;

    // CSR build (g_deg zeroed: load-time init + reset in k_scan3 each run)
    k_count<<<(EE + 511) / 512, 512>>>(dst);
    k_scan1<<<NB_SCAN, 1024>>>();
    k_scan3<<<(NN + 255) / 256, 256>>>(NB_SCAN);
    k_fill<<<(EE + 511) / 512, 512>>>(src, dst);

    // layers
    k_gemm_mma<96><<<GT, 256>>>(x, W1, 0, 128, 0);
    k_agg96<<<AB, 256>>>(b1);
    k_gemm_mma<96><<<GT, 256>>>(x, W2, 1, 96, 1);
    k_agg96<<<AB, 256>>>(b2);
    k_gemm_mma<32><<<GT, 256>>>(x, W3, 1, 96, 1);
    k_agg32lsm<<<AB, 256>>>(b3, out);
}